// round 11
// baseline (speedup 1.0000x reference)
#include <cuda_runtime.h>

// MinConv2d: 3x3 min-pool, stride 1, pad 1 (zero padding PARTICIPATES in min).
// Input/output: (8, 64, 512, 512) fp32 -> 512 planes of 512x512.
//
// R10 = R8 resubmitted (previous run was a container infra failure):
// R3 structure (separable rolling min, batch-4 clamped loads, direct L1-hit
// edge scalars) with:
//  - __launch_bounds__(128, 12): cap regs at 40 -> 12 blocks/SM (75% occ)
//  - ROWS_PER_BLOCK 64: halo re-read 1.031x, longer-lived blocks.

#define PLANE_H 512
#define PLANE_W 512
#define ROWS_PER_BLOCK 64
#define THREADS 128   // 128 * 4 floats = 512 = full row width

__device__ __forceinline__ float4 fmin4(float4 a, float4 b) {
    return make_float4(fminf(a.x, b.x), fminf(a.y, b.y),
                       fminf(a.z, b.z), fminf(a.w, b.w));
}

__device__ __forceinline__ float4 hmin_row(float4 v, float l, float r, bool valid) {
    float4 h;
    h.x = fminf(l,   fminf(v.x, v.y));
    h.y = fminf(v.x, fminf(v.y, v.z));
    h.z = fminf(v.y, fminf(v.z, v.w));
    h.w = fminf(v.z, fminf(v.w, r));
    if (!valid) h = make_float4(0.f, 0.f, 0.f, 0.f);
    return h;
}

__global__ __launch_bounds__(THREADS, 12)
void minpool3x3_kernel(const float* __restrict__ x, float* __restrict__ out) {
    const int plane = blockIdx.y;
    const float* __restrict__ xp = x + (size_t)plane * PLANE_H * PLANE_W;
    float* __restrict__ op = out + (size_t)plane * PLANE_H * PLANE_W;

    const int base  = threadIdx.x * 4;
    const int y0    = blockIdx.x * ROWS_PER_BLOCK;
    const bool hasL = (base != 0);
    const bool hasR = (base + 4 != PLANE_W);

    // ---- prologue: input rows y0-1 and y0 ----
    float4 h2, h1;
    {
        const int yi = y0 - 1;
        const int yc = yi < 0 ? 0 : yi;                  // clamped, always legal
        const float* row = xp + (size_t)yc * PLANE_W + base;
        float4 v = *reinterpret_cast<const float4*>(row);
        float  l = hasL ? __ldg(row - 1) : 0.0f;
        float  r = hasR ? __ldg(row + 4) : 0.0f;
        h2 = hmin_row(v, l, r, yi >= 0);
    }
    {
        const float* row = xp + (size_t)y0 * PLANE_W + base;
        float4 v = *reinterpret_cast<const float4*>(row);
        float  l = hasL ? __ldg(row - 1) : 0.0f;
        float  r = hasR ? __ldg(row + 4) : 0.0f;
        h1 = hmin_row(v, l, r, true);
    }

    // ---- steady state: input rows y0+1 .. y0+64, batched 4 at a time ----
    for (int r0 = 1; r0 <= ROWS_PER_BLOCK; r0 += 4) {
        float4 v[4];
        float  L[4], R[4];
        bool   val[4];

        #pragma unroll
        for (int j = 0; j < 4; ++j) {
            const int yi = y0 + r0 + j;                       // may be 512 (pad)
            const int yc = yi < PLANE_H ? yi : PLANE_H - 1;   // clamp: load legal
            const float* row = xp + (size_t)yc * PLANE_W + base;
            v[j]   = *reinterpret_cast<const float4*>(row);
            L[j]   = hasL ? __ldg(row - 1) : 0.0f;
            R[j]   = hasR ? __ldg(row + 4) : 0.0f;
            val[j] = yi < PLANE_H;
        }

        #pragma unroll
        for (int j = 0; j < 4; ++j) {
            const float4 h = hmin_row(v[j], L[j], R[j], val[j]);
            const int yo = y0 + r0 + j - 1;                   // output row done
            *reinterpret_cast<float4*>(op + (size_t)yo * PLANE_W + base) =
                fmin4(h2, fmin4(h1, h));
            h2 = h1;
            h1 = h;
        }
    }
}

extern "C" void kernel_launch(void* const* d_in, const int* in_sizes, int n_in,
                              void* d_out, int out_size) {
    const float* x = (const float*)d_in[0];
    float* out = (float*)d_out;

    const int planes = 8 * 64;                       // 512
    dim3 grid(PLANE_H / ROWS_PER_BLOCK, planes);     // (8, 512) = 4096 blocks
    dim3 block(THREADS);
    minpool3x3_kernel<<<grid, block>>>(x, out);
}

// round 16
// speedup vs baseline: 1.0433x; 1.0433x over previous
#include <cuda_runtime.h>

// MinConv2d: 3x3 min-pool, stride 1, pad 1 (zero padding PARTICIPATES in min).
// Input/output: (8, 64, 512, 512) fp32 -> 512 planes of 512x512.
//
// R11: separable rolling min with BATCH-8 front-loaded row loads
// (8 independent float4 DRAM loads in flight per thread), ROWS_PER_BLOCK=64,
// no register cap. Occupancy drops to ~50% but in-flight bytes per SM nearly
// double vs R3.

#define PLANE_H 512
#define PLANE_W 512
#define ROWS_PER_BLOCK 64
#define BATCH 8
#define THREADS 128   // 128 * 4 floats = 512 = full row width

__device__ __forceinline__ float4 fmin4(float4 a, float4 b) {
    return make_float4(fminf(a.x, b.x), fminf(a.y, b.y),
                       fminf(a.z, b.z), fminf(a.w, b.w));
}

__device__ __forceinline__ float4 hmin_row(float4 v, float l, float r, bool valid) {
    float4 h;
    h.x = fminf(l,   fminf(v.x, v.y));
    h.y = fminf(v.x, fminf(v.y, v.z));
    h.z = fminf(v.y, fminf(v.z, v.w));
    h.w = fminf(v.z, fminf(v.w, r));
    if (!valid) h = make_float4(0.f, 0.f, 0.f, 0.f);
    return h;
}

__global__ __launch_bounds__(THREADS)
void minpool3x3_kernel(const float* __restrict__ x, float* __restrict__ out) {
    const int plane = blockIdx.y;
    const float* __restrict__ xp = x + (size_t)plane * PLANE_H * PLANE_W;
    float* __restrict__ op = out + (size_t)plane * PLANE_H * PLANE_W;

    const int base  = threadIdx.x * 4;
    const int y0    = blockIdx.x * ROWS_PER_BLOCK;
    const bool hasL = (base != 0);
    const bool hasR = (base + 4 != PLANE_W);

    // ---- prologue: input rows y0-1 and y0 ----
    float4 h2, h1;
    {
        const int yi = y0 - 1;
        const int yc = yi < 0 ? 0 : yi;                  // clamped, always legal
        const float* row = xp + (size_t)yc * PLANE_W + base;
        float4 v = *reinterpret_cast<const float4*>(row);
        float  l = hasL ? __ldg(row - 1) : 0.0f;
        float  r = hasR ? __ldg(row + 4) : 0.0f;
        h2 = hmin_row(v, l, r, yi >= 0);
    }
    {
        const float* row = xp + (size_t)y0 * PLANE_W + base;
        float4 v = *reinterpret_cast<const float4*>(row);
        float  l = hasL ? __ldg(row - 1) : 0.0f;
        float  r = hasR ? __ldg(row + 4) : 0.0f;
        h1 = hmin_row(v, l, r, true);
    }

    // ---- steady state: input rows y0+1 .. y0+64, batched 8 at a time ----
    for (int r0 = 1; r0 <= ROWS_PER_BLOCK; r0 += BATCH) {
        float4 v[BATCH];
        float  L[BATCH], R[BATCH];
        bool   val[BATCH];

        #pragma unroll
        for (int j = 0; j < BATCH; ++j) {
            const int yi = y0 + r0 + j;                       // may be 512 (pad)
            const int yc = yi < PLANE_H ? yi : PLANE_H - 1;   // clamp: load legal
            const float* row = xp + (size_t)yc * PLANE_W + base;
            v[j]   = *reinterpret_cast<const float4*>(row);
            L[j]   = hasL ? __ldg(row - 1) : 0.0f;
            R[j]   = hasR ? __ldg(row + 4) : 0.0f;
            val[j] = yi < PLANE_H;
        }

        #pragma unroll
        for (int j = 0; j < BATCH; ++j) {
            const float4 h = hmin_row(v[j], L[j], R[j], val[j]);
            const int yo = y0 + r0 + j - 1;                   // output row done
            *reinterpret_cast<float4*>(op + (size_t)yo * PLANE_W + base) =
                fmin4(h2, fmin4(h1, h));
            h2 = h1;
            h1 = h;
        }
    }
}

extern "C" void kernel_launch(void* const* d_in, const int* in_sizes, int n_in,
                              void* d_out, int out_size) {
    const float* x = (const float*)d_in[0];
    float* out = (float*)d_out;

    const int planes = 8 * 64;                       // 512
    dim3 grid(PLANE_H / ROWS_PER_BLOCK, planes);     // (8, 512) = 4096 blocks
    dim3 block(THREADS);
    minpool3x3_kernel<<<grid, block>>>(x, out);
}